// round 4
// baseline (speedup 1.0000x reference)
#include <cuda_runtime.h>
#include <cuda_bf16.h>

// Problem constants (fixed by the dataset)
#define N_NODES_MAX 50048
#define N_EDGES_MAX 800000
#define IN_FEATS    128
#define NUM_HEADS   4
#define OUT_FEATS   32
#define HD          (NUM_HEADS * OUT_FEATS)   // 128

// Scratch (static __device__ arrays; no allocation allowed)
__device__ float g_ft[N_NODES_MAX * HD];     // projected features [N,128]
__device__ int   g_cnt[N_NODES_MAX];         // in-degree histogram
__device__ int   g_off[N_NODES_MAX];         // CSR row starts (exclusive scan)
__device__ int   g_cur[N_NODES_MAX];         // scatter cursors
__device__ int   g_csr_src[N_EDGES_MAX];     // src node per CSR slot

// ---------------------------------------------------------------------------
// K0: zero the degree histogram
// ---------------------------------------------------------------------------
__global__ void zero_cnt_kernel(int n) {
    int i = blockIdx.x * blockDim.x + threadIdx.x;
    if (i < n) g_cnt[i] = 0;
}

// ---------------------------------------------------------------------------
// K1: in-degree histogram
// ---------------------------------------------------------------------------
__global__ void hist_kernel(const int* __restrict__ dst, int E) {
    int i = blockIdx.x * blockDim.x + threadIdx.x;
    if (i < E) atomicAdd(&g_cnt[dst[i]], 1);
}

// ---------------------------------------------------------------------------
// K2: single-block exclusive scan over g_cnt -> g_off (+ g_cur copy).
// 1024 threads; each owns a contiguous chunk of ~49 nodes. Per-thread
// sequential sum, block scan of the 1024 totals (warp scans + warp-0 scan of
// warp sums), then a second sequential pass writes running offsets.
// ---------------------------------------------------------------------------
#define SCAN_T 1024
__global__ void scan_kernel(int N) {
    const int t = threadIdx.x;
    const int CH = (N + SCAN_T - 1) / SCAN_T;
    const int beg = t * CH;
    const int end = min(beg + CH, N);

    int sum = 0;
    for (int i = beg; i < end; i++) sum += g_cnt[i];

    // block exclusive scan of per-thread sums
    const int lane = t & 31, w = t >> 5;
    int x = sum;
    #pragma unroll
    for (int o = 1; o < 32; o <<= 1) {
        int y = __shfl_up_sync(0xffffffffu, x, o);
        if (lane >= o) x += y;
    }
    __shared__ int wtot[32];
    if (lane == 31) wtot[w] = x;
    __syncthreads();
    if (w == 0) {
        int y = wtot[lane];
        int z = y;
        #pragma unroll
        for (int o = 1; o < 32; o <<= 1) {
            int u = __shfl_up_sync(0xffffffffu, z, o);
            if (lane >= o) z += u;
        }
        wtot[lane] = z - y;   // exclusive warp offsets
    }
    __syncthreads();

    int run = (x - sum) + wtot[w];   // exclusive prefix for this thread
    for (int i = beg; i < end; i++) {
        int c = g_cnt[i];
        g_off[i] = run;
        g_cur[i] = run;
        run += c;
    }
}

// ---------------------------------------------------------------------------
// K3: scatter src ids into CSR slots
// ---------------------------------------------------------------------------
__global__ void scatter_kernel(const int* __restrict__ src,
                               const int* __restrict__ dst, int E) {
    int i = blockIdx.x * blockDim.x + threadIdx.x;
    if (i < E) {
        int pos = atomicAdd(&g_cur[dst[i]], 1);
        g_csr_src[pos] = src[i];
    }
}

// ---------------------------------------------------------------------------
// K4: projection GEMM. ft[n][o] = sum_k feat[n][k] * W[o][k]
// Tiled SGEMM: BM=32 rows, BN=128 cols (all), BK=32. 256 threads, 4x4 microtile.
// Runs on a forked stream, concurrent with the CSR build.
// ---------------------------------------------------------------------------
#define BM 32
#define BK 32
__global__ void gemm_kernel(const float* __restrict__ feat,
                            const float* __restrict__ W,
                            int N) {
    __shared__ float As[BK][BM];    // feat tile, transposed: As[k][r]
    __shared__ float Bs[BK][HD];    // W tile, transposed:   Bs[k][o]

    const int tid = threadIdx.x;          // 0..255
    const int cc  = tid & 31;
    const int rr  = tid >> 5;
    const int row0 = blockIdx.x * BM;

    float acc[4][4];
    #pragma unroll
    for (int i = 0; i < 4; i++)
        #pragma unroll
        for (int j = 0; j < 4; j++) acc[i][j] = 0.0f;

    for (int kc = 0; kc < IN_FEATS; kc += BK) {
        {
            int r  = tid >> 3;
            int k4 = (tid & 7) << 2;
            float4 v = make_float4(0.f, 0.f, 0.f, 0.f);
            if (row0 + r < N)
                v = *(const float4*)&feat[(size_t)(row0 + r) * IN_FEATS + kc + k4];
            As[k4 + 0][r] = v.x; As[k4 + 1][r] = v.y;
            As[k4 + 2][r] = v.z; As[k4 + 3][r] = v.w;
        }
        #pragma unroll
        for (int it = 0; it < 4; it++) {
            int idx = tid + it * 256;
            int o   = idx >> 3;
            int k4  = (idx & 7) << 2;
            float4 v = *(const float4*)&W[(size_t)o * IN_FEATS + kc + k4];
            Bs[k4 + 0][o] = v.x; Bs[k4 + 1][o] = v.y;
            Bs[k4 + 2][o] = v.z; Bs[k4 + 3][o] = v.w;
        }
        __syncthreads();

        #pragma unroll
        for (int k = 0; k < BK; k++) {
            float4 a = *(const float4*)&As[k][rr << 2];
            float4 b = *(const float4*)&Bs[k][cc << 2];
            acc[0][0] += a.x * b.x; acc[0][1] += a.x * b.y; acc[0][2] += a.x * b.z; acc[0][3] += a.x * b.w;
            acc[1][0] += a.y * b.x; acc[1][1] += a.y * b.y; acc[1][2] += a.y * b.z; acc[1][3] += a.y * b.w;
            acc[2][0] += a.z * b.x; acc[2][1] += a.z * b.y; acc[2][2] += a.z * b.z; acc[2][3] += a.z * b.w;
            acc[3][0] += a.w * b.x; acc[3][1] += a.w * b.y; acc[3][2] += a.w * b.z; acc[3][3] += a.w * b.w;
        }
        __syncthreads();
    }

    #pragma unroll
    for (int i = 0; i < 4; i++) {
        int r = row0 + (rr << 2) + i;
        if (r < N) {
            float4 v = make_float4(acc[i][0], acc[i][1], acc[i][2], acc[i][3]);
            *(float4*)&g_ft[(size_t)r * HD + (cc << 2)] = v;
        }
    }
}

// ---------------------------------------------------------------------------
// K5: atomic-free aggregation. One warp per DST node, software-pipelined:
// the ft[src] gather for edge t+1 is issued BEFORE the shuffle-reduce /
// exp chain of edge t, doubling per-warp memory-level parallelism.
// ft[dst] held in registers (1 float4/lane). No atomics anywhere.
// Max-subtraction skipped: mathematically identical softmax; |p*scale| <~ 7.
// ---------------------------------------------------------------------------
__global__ void agg_kernel(float* __restrict__ out, int N) {
    const int node = (blockIdx.x * blockDim.x + threadIdx.x) >> 5;
    if (node >= N) return;
    const int lane = threadIdx.x & 31;

    const int start = g_off[node];
    const int deg   = g_cnt[node];

    const float4* ft4 = (const float4*)g_ft;
    const float4 b4 = ft4[(size_t)node * 32 + lane];

    float4 acc = make_float4(0.f, 0.f, 0.f, 0.f);
    float s = 0.0f;
    const float scale = 0.17677669529663687f;  // 1/sqrt(32)

    for (int base = 0; base < deg; base += 32) {
        int j = base + lane;
        int sj = (j < deg) ? g_csr_src[start + j] : 0;
        int cnt = min(32, deg - base);

        // prologue: issue first gather of the chunk
        int sn0 = __shfl_sync(0xffffffffu, sj, 0);
        float4 a4 = ft4[(size_t)sn0 * 32 + lane];

        #pragma unroll 2
        for (int t = 0; t < cnt; t++) {
            float4 cur = a4;
            if (t + 1 < cnt) {   // prefetch next edge's row
                int sn = __shfl_sync(0xffffffffu, sj, t + 1);
                a4 = ft4[(size_t)sn * 32 + lane];
            }
            float p = cur.x * b4.x + cur.y * b4.y + cur.z * b4.z + cur.w * b4.w;
            p += __shfl_xor_sync(0xffffffffu, p, 4);
            p += __shfl_xor_sync(0xffffffffu, p, 2);
            p += __shfl_xor_sync(0xffffffffu, p, 1);
            float e = __expf(p * scale);
            s += e;
            acc.x += e * cur.x; acc.y += e * cur.y;
            acc.z += e * cur.z; acc.w += e * cur.w;
        }
    }

    float inv = (deg > 0) ? (1.0f / s) : 0.0f;
    float4 r = make_float4(acc.x * inv, acc.y * inv, acc.z * inv, acc.w * inv);
    ((float4*)out)[(size_t)node * 32 + lane] = r;
}

// ---------------------------------------------------------------------------
extern "C" void kernel_launch(void* const* d_in, const int* in_sizes, int n_in,
                              void* d_out, int out_size) {
    const float* feat = (const float*)d_in[0];
    const float* W    = (const float*)d_in[1];
    const int*   src  = (const int*)d_in[2];
    const int*   dst  = (const int*)d_in[3];
    float* out = (float*)d_out;

    const int N = in_sizes[0] / IN_FEATS;   // 50000
    const int E = in_sizes[2];              // 800000

    // Persistent side stream + fork/join events (created once; resources only,
    // the captured work per call is identical every time).
    static cudaStream_t s_gemm = nullptr;
    static cudaEvent_t  ev_fork = nullptr, ev_join = nullptr;
    if (s_gemm == nullptr) {
        cudaStreamCreateWithFlags(&s_gemm, cudaStreamNonBlocking);
        cudaEventCreateWithFlags(&ev_fork, cudaEventDisableTiming);
        cudaEventCreateWithFlags(&ev_join, cudaEventDisableTiming);
    }

    // ---- fork: GEMM branch (depends only on feat, W) ----
    cudaEventRecord(ev_fork, 0);
    cudaStreamWaitEvent(s_gemm, ev_fork, 0);
    gemm_kernel<<<(N + BM - 1) / BM, 256, 0, s_gemm>>>(feat, W, N);
    cudaEventRecord(ev_join, s_gemm);

    // ---- main stream: CSR build branch (depends only on src, dst) ----
    zero_cnt_kernel<<<(N + 255) / 256, 256>>>(N);
    hist_kernel<<<(E + 255) / 256, 256>>>(dst, E);
    scan_kernel<<<1, SCAN_T>>>(N);
    scatter_kernel<<<(E + 255) / 256, 256>>>(src, dst, E);

    // ---- join, then aggregate ----
    cudaStreamWaitEvent(0, ev_join, 0);
    {
        int warps_per_block = 8;  // 256 threads
        int blocks = (N + warps_per_block - 1) / warps_per_block;
        agg_kernel<<<blocks, 256>>>(out, N);
    }
}

// round 5
// speedup vs baseline: 1.5213x; 1.5213x over previous
#include <cuda_runtime.h>
#include <cuda_bf16.h>

// Problem constants (fixed by the dataset)
#define N_NODES_MAX 50048
#define N_EDGES_MAX 800000
#define IN_FEATS    128
#define NUM_HEADS   4
#define OUT_FEATS   32
#define HD          (NUM_HEADS * OUT_FEATS)   // 128

#define SCAN_B 1024
#define MAX_BLOCKS ((N_NODES_MAX + SCAN_B - 1) / SCAN_B + 2)

// Scratch (static __device__ arrays; no allocation allowed)
__device__ float g_ft[N_NODES_MAX * HD];     // projected features [N,128]
__device__ int   g_cnt[N_NODES_MAX];         // in-degree histogram
__device__ int   g_off[N_NODES_MAX];         // CSR row starts (exclusive scan)
__device__ int   g_cur[N_NODES_MAX];         // scatter cursors
__device__ int   g_bsum[MAX_BLOCKS];         // block partial sums for scan
__device__ int   g_csr_src[N_EDGES_MAX];     // src node per CSR slot

// ---------------------------------------------------------------------------
// K0: zero the degree histogram
// ---------------------------------------------------------------------------
__global__ void zero_cnt_kernel(int n) {
    int i = blockIdx.x * blockDim.x + threadIdx.x;
    if (i < n) g_cnt[i] = 0;
}

// ---------------------------------------------------------------------------
// K1: in-degree histogram
// ---------------------------------------------------------------------------
__global__ void hist_kernel(const int* __restrict__ dst, int E) {
    int i = blockIdx.x * blockDim.x + threadIdx.x;
    if (i < E) atomicAdd(&g_cnt[dst[i]], 1);
}

// ---------------------------------------------------------------------------
// K2a/K2b/K2c: 3-phase exclusive scan over g_cnt -> g_off (+ g_cur copy).
// Multi-block, fully coalesced (the single-block variant serialized ~150K
// uncoalesced LSU ops through one SM: 77us. Never again.)
// ---------------------------------------------------------------------------
__global__ void scan_phase1(int N) {
    int i = blockIdx.x * SCAN_B + threadIdx.x;
    int v = (i < N) ? g_cnt[i] : 0;
    #pragma unroll
    for (int o = 16; o > 0; o >>= 1) v += __shfl_xor_sync(0xffffffffu, v, o);
    __shared__ int wsum[32];
    int lane = threadIdx.x & 31, w = threadIdx.x >> 5;
    if (lane == 0) wsum[w] = v;
    __syncthreads();
    if (w == 0) {
        int x = wsum[lane];
        #pragma unroll
        for (int o = 16; o > 0; o >>= 1) x += __shfl_xor_sync(0xffffffffu, x, o);
        if (lane == 0) g_bsum[blockIdx.x] = x;
    }
}

__global__ void scan_phase2(int nb) {
    __shared__ int sh[64];
    int t = threadIdx.x;
    int v = (t < nb) ? g_bsum[t] : 0;
    sh[t] = v;
    __syncthreads();
    #pragma unroll
    for (int o = 1; o < 64; o <<= 1) {
        int x = (t >= o) ? sh[t - o] : 0;
        __syncthreads();
        sh[t] += x;
        __syncthreads();
    }
    if (t < nb) g_bsum[t] = sh[t] - v;   // exclusive
}

__global__ void scan_phase3(int N) {
    int i = blockIdx.x * SCAN_B + threadIdx.x;
    int v = (i < N) ? g_cnt[i] : 0;
    int lane = threadIdx.x & 31, w = threadIdx.x >> 5;
    int x = v;
    #pragma unroll
    for (int o = 1; o < 32; o <<= 1) {
        int y = __shfl_up_sync(0xffffffffu, x, o);
        if (lane >= o) x += y;
    }
    __shared__ int woff[32];
    if (lane == 31) woff[w] = x;
    __syncthreads();
    if (w == 0) {
        int y = woff[lane];
        int z = y;
        #pragma unroll
        for (int o = 1; o < 32; o <<= 1) {
            int t2 = __shfl_up_sync(0xffffffffu, z, o);
            if (lane >= o) z += t2;
        }
        woff[lane] = z - y;   // exclusive warp offsets
    }
    __syncthreads();
    int excl = (x - v) + woff[w] + g_bsum[blockIdx.x];
    if (i < N) { g_off[i] = excl; g_cur[i] = excl; }
}

// ---------------------------------------------------------------------------
// K3: scatter src ids into CSR slots
// ---------------------------------------------------------------------------
__global__ void scatter_kernel(const int* __restrict__ src,
                               const int* __restrict__ dst, int E) {
    int i = blockIdx.x * blockDim.x + threadIdx.x;
    if (i < E) {
        int pos = atomicAdd(&g_cur[dst[i]], 1);
        g_csr_src[pos] = src[i];
    }
}

// ---------------------------------------------------------------------------
// K4: projection GEMM. ft[n][o] = sum_k feat[n][k] * W[o][k]
// Tiled SGEMM: BM=32 rows, BN=128 cols (all), BK=32. 256 threads, 4x4 microtile.
// Runs on a forked stream, concurrent with the CSR build.
// ---------------------------------------------------------------------------
#define BM 32
#define BK 32
__global__ void gemm_kernel(const float* __restrict__ feat,
                            const float* __restrict__ W,
                            int N) {
    __shared__ float As[BK][BM];    // feat tile, transposed: As[k][r]
    __shared__ float Bs[BK][HD];    // W tile, transposed:   Bs[k][o]

    const int tid = threadIdx.x;          // 0..255
    const int cc  = tid & 31;
    const int rr  = tid >> 5;
    const int row0 = blockIdx.x * BM;

    float acc[4][4];
    #pragma unroll
    for (int i = 0; i < 4; i++)
        #pragma unroll
        for (int j = 0; j < 4; j++) acc[i][j] = 0.0f;

    for (int kc = 0; kc < IN_FEATS; kc += BK) {
        {
            int r  = tid >> 3;
            int k4 = (tid & 7) << 2;
            float4 v = make_float4(0.f, 0.f, 0.f, 0.f);
            if (row0 + r < N)
                v = *(const float4*)&feat[(size_t)(row0 + r) * IN_FEATS + kc + k4];
            As[k4 + 0][r] = v.x; As[k4 + 1][r] = v.y;
            As[k4 + 2][r] = v.z; As[k4 + 3][r] = v.w;
        }
        #pragma unroll
        for (int it = 0; it < 4; it++) {
            int idx = tid + it * 256;
            int o   = idx >> 3;
            int k4  = (idx & 7) << 2;
            float4 v = *(const float4*)&W[(size_t)o * IN_FEATS + kc + k4];
            Bs[k4 + 0][o] = v.x; Bs[k4 + 1][o] = v.y;
            Bs[k4 + 2][o] = v.z; Bs[k4 + 3][o] = v.w;
        }
        __syncthreads();

        #pragma unroll
        for (int k = 0; k < BK; k++) {
            float4 a = *(const float4*)&As[k][rr << 2];
            float4 b = *(const float4*)&Bs[k][cc << 2];
            acc[0][0] += a.x * b.x; acc[0][1] += a.x * b.y; acc[0][2] += a.x * b.z; acc[0][3] += a.x * b.w;
            acc[1][0] += a.y * b.x; acc[1][1] += a.y * b.y; acc[1][2] += a.y * b.z; acc[1][3] += a.y * b.w;
            acc[2][0] += a.z * b.x; acc[2][1] += a.z * b.y; acc[2][2] += a.z * b.z; acc[2][3] += a.z * b.w;
            acc[3][0] += a.w * b.x; acc[3][1] += a.w * b.y; acc[3][2] += a.w * b.z; acc[3][3] += a.w * b.w;
        }
        __syncthreads();
    }

    #pragma unroll
    for (int i = 0; i < 4; i++) {
        int r = row0 + (rr << 2) + i;
        if (r < N) {
            float4 v = make_float4(acc[i][0], acc[i][1], acc[i][2], acc[i][3]);
            *(float4*)&g_ft[(size_t)r * HD + (cc << 2)] = v;
        }
    }
}

// ---------------------------------------------------------------------------
// K5: atomic-free aggregation. One warp per DST node, software-pipelined:
// the ft[src] gather for edge t+1 is issued BEFORE the shuffle-reduce /
// exp chain of edge t, doubling per-warp memory-level parallelism.
// ft[dst] held in registers (1 float4/lane). No atomics anywhere.
// Max-subtraction skipped: mathematically identical softmax; |p*scale| <~ 7.
// ---------------------------------------------------------------------------
__global__ void agg_kernel(float* __restrict__ out, int N) {
    const int node = (blockIdx.x * blockDim.x + threadIdx.x) >> 5;
    if (node >= N) return;
    const int lane = threadIdx.x & 31;

    const int start = g_off[node];
    const int deg   = g_cnt[node];

    const float4* ft4 = (const float4*)g_ft;
    const float4 b4 = ft4[(size_t)node * 32 + lane];

    float4 acc = make_float4(0.f, 0.f, 0.f, 0.f);
    float s = 0.0f;
    const float scale = 0.17677669529663687f;  // 1/sqrt(32)

    for (int base = 0; base < deg; base += 32) {
        int j = base + lane;
        int sj = (j < deg) ? g_csr_src[start + j] : 0;
        int cnt = min(32, deg - base);

        // prologue: issue first gather of the chunk
        int sn0 = __shfl_sync(0xffffffffu, sj, 0);
        float4 a4 = ft4[(size_t)sn0 * 32 + lane];

        #pragma unroll 2
        for (int t = 0; t < cnt; t++) {
            float4 cur = a4;
            if (t + 1 < cnt) {   // prefetch next edge's row
                int sn = __shfl_sync(0xffffffffu, sj, t + 1);
                a4 = ft4[(size_t)sn * 32 + lane];
            }
            float p = cur.x * b4.x + cur.y * b4.y + cur.z * b4.z + cur.w * b4.w;
            p += __shfl_xor_sync(0xffffffffu, p, 4);
            p += __shfl_xor_sync(0xffffffffu, p, 2);
            p += __shfl_xor_sync(0xffffffffu, p, 1);
            float e = __expf(p * scale);
            s += e;
            acc.x += e * cur.x; acc.y += e * cur.y;
            acc.z += e * cur.z; acc.w += e * cur.w;
        }
    }

    float inv = (deg > 0) ? (1.0f / s) : 0.0f;
    float4 r = make_float4(acc.x * inv, acc.y * inv, acc.z * inv, acc.w * inv);
    ((float4*)out)[(size_t)node * 32 + lane] = r;
}

// ---------------------------------------------------------------------------
extern "C" void kernel_launch(void* const* d_in, const int* in_sizes, int n_in,
                              void* d_out, int out_size) {
    const float* feat = (const float*)d_in[0];
    const float* W    = (const float*)d_in[1];
    const int*   src  = (const int*)d_in[2];
    const int*   dst  = (const int*)d_in[3];
    float* out = (float*)d_out;

    const int N = in_sizes[0] / IN_FEATS;   // 50000
    const int E = in_sizes[2];              // 800000

    const int nb = (N + SCAN_B - 1) / SCAN_B;

    // Persistent side stream + fork/join events (created once; resources only,
    // the captured work per call is identical every time).
    static cudaStream_t s_gemm = nullptr;
    static cudaEvent_t  ev_fork = nullptr, ev_join = nullptr;
    if (s_gemm == nullptr) {
        cudaStreamCreateWithFlags(&s_gemm, cudaStreamNonBlocking);
        cudaEventCreateWithFlags(&ev_fork, cudaEventDisableTiming);
        cudaEventCreateWithFlags(&ev_join, cudaEventDisableTiming);
    }

    // ---- fork: GEMM branch (depends only on feat, W) ----
    cudaEventRecord(ev_fork, 0);
    cudaStreamWaitEvent(s_gemm, ev_fork, 0);
    gemm_kernel<<<(N + BM - 1) / BM, 256, 0, s_gemm>>>(feat, W, N);
    cudaEventRecord(ev_join, s_gemm);

    // ---- main stream: CSR build branch (depends only on src, dst) ----
    zero_cnt_kernel<<<(N + 255) / 256, 256>>>(N);
    hist_kernel<<<(E + 255) / 256, 256>>>(dst, E);
    scan_phase1<<<nb, SCAN_B>>>(N);
    scan_phase2<<<1, 64>>>(nb);
    scan_phase3<<<nb, SCAN_B>>>(N);
    scatter_kernel<<<(E + 255) / 256, 256>>>(src, dst, E);

    // ---- join, then aggregate ----
    cudaStreamWaitEvent(0, ev_join, 0);
    {
        int warps_per_block = 8;  // 256 threads
        int blocks = (N + warps_per_block - 1) / warps_per_block;
        agg_kernel<<<blocks, 256>>>(out, N);
    }
}

// round 6
// speedup vs baseline: 1.7681x; 1.1622x over previous
#include <cuda_runtime.h>
#include <cuda_bf16.h>

// Problem constants (fixed by the dataset)
#define N_NODES_MAX 50048
#define N_EDGES_MAX 800000
#define IN_FEATS    128
#define NUM_HEADS   4
#define OUT_FEATS   32
#define HD          (NUM_HEADS * OUT_FEATS)   // 128

#define SCAN_B 1024
#define MAX_BLOCKS ((N_NODES_MAX + SCAN_B - 1) / SCAN_B + 2)

// Scratch (static __device__ arrays; no allocation allowed)
__device__ float g_ft[N_NODES_MAX * HD];     // projected features [N,128]
__device__ int   g_cnt[N_NODES_MAX];         // in-degree histogram
__device__ int   g_off[N_NODES_MAX];         // CSR row starts (exclusive scan)
__device__ int   g_cur[N_NODES_MAX];         // scatter cursors
__device__ int   g_bsum[MAX_BLOCKS];         // block partial sums for scan
__device__ int   g_csr_src[N_EDGES_MAX];     // src node per CSR slot

// ---------------------------------------------------------------------------
// K0: zero the degree histogram
// ---------------------------------------------------------------------------
__global__ void zero_cnt_kernel(int n) {
    int i = blockIdx.x * blockDim.x + threadIdx.x;
    if (i < n) g_cnt[i] = 0;
}

// ---------------------------------------------------------------------------
// K1: in-degree histogram
// ---------------------------------------------------------------------------
__global__ void hist_kernel(const int* __restrict__ dst, int E) {
    int i = blockIdx.x * blockDim.x + threadIdx.x;
    if (i < E) atomicAdd(&g_cnt[dst[i]], 1);
}

// ---------------------------------------------------------------------------
// K2a/K2b/K2c: 3-phase exclusive scan over g_cnt -> g_off (+ g_cur copy).
// Multi-block, fully coalesced.
// ---------------------------------------------------------------------------
__global__ void scan_phase1(int N) {
    int i = blockIdx.x * SCAN_B + threadIdx.x;
    int v = (i < N) ? g_cnt[i] : 0;
    #pragma unroll
    for (int o = 16; o > 0; o >>= 1) v += __shfl_xor_sync(0xffffffffu, v, o);
    __shared__ int wsum[32];
    int lane = threadIdx.x & 31, w = threadIdx.x >> 5;
    if (lane == 0) wsum[w] = v;
    __syncthreads();
    if (w == 0) {
        int x = wsum[lane];
        #pragma unroll
        for (int o = 16; o > 0; o >>= 1) x += __shfl_xor_sync(0xffffffffu, x, o);
        if (lane == 0) g_bsum[blockIdx.x] = x;
    }
}

__global__ void scan_phase2(int nb) {
    __shared__ int sh[64];
    int t = threadIdx.x;
    int v = (t < nb) ? g_bsum[t] : 0;
    sh[t] = v;
    __syncthreads();
    #pragma unroll
    for (int o = 1; o < 64; o <<= 1) {
        int x = (t >= o) ? sh[t - o] : 0;
        __syncthreads();
        sh[t] += x;
        __syncthreads();
    }
    if (t < nb) g_bsum[t] = sh[t] - v;   // exclusive
}

__global__ void scan_phase3(int N) {
    int i = blockIdx.x * SCAN_B + threadIdx.x;
    int v = (i < N) ? g_cnt[i] : 0;
    int lane = threadIdx.x & 31, w = threadIdx.x >> 5;
    int x = v;
    #pragma unroll
    for (int o = 1; o < 32; o <<= 1) {
        int y = __shfl_up_sync(0xffffffffu, x, o);
        if (lane >= o) x += y;
    }
    __shared__ int woff[32];
    if (lane == 31) woff[w] = x;
    __syncthreads();
    if (w == 0) {
        int y = woff[lane];
        int z = y;
        #pragma unroll
        for (int o = 1; o < 32; o <<= 1) {
            int t2 = __shfl_up_sync(0xffffffffu, z, o);
            if (lane >= o) z += t2;
        }
        woff[lane] = z - y;   // exclusive warp offsets
    }
    __syncthreads();
    int excl = (x - v) + woff[w] + g_bsum[blockIdx.x];
    if (i < N) { g_off[i] = excl; g_cur[i] = excl; }
}

// ---------------------------------------------------------------------------
// K3: scatter src ids into CSR slots
// ---------------------------------------------------------------------------
__global__ void scatter_kernel(const int* __restrict__ src,
                               const int* __restrict__ dst, int E) {
    int i = blockIdx.x * blockDim.x + threadIdx.x;
    if (i < E) {
        int pos = atomicAdd(&g_cur[dst[i]], 1);
        g_csr_src[pos] = src[i];
    }
}

// ---------------------------------------------------------------------------
// K4: projection GEMM. ft[n][o] = sum_k feat[n][k] * W[o][k]
// BM=128 x BN=128 tile, BK=16, 256 threads, 8x8 microtile:
// 64 FFMA per 4 LDS.128 (As reads broadcast in-warp, Bs reads conflict-free).
// Register-staged prefetch: LDGs for k-block t+1 issue before compute of t.
// Runs on a forked stream, concurrent with the CSR build.
// ---------------------------------------------------------------------------
#define GM 128
#define GK 16
__global__ void __launch_bounds__(256, 2)
gemm_kernel(const float* __restrict__ feat,
            const float* __restrict__ W,
            int N) {
    __shared__ float As[GK][GM];    // feat tile, transposed: As[k][r]   8KB
    __shared__ float Bs[GK][HD];    // W tile, transposed:    Bs[k][o]   8KB

    const int tid = threadIdx.x;           // 0..255
    const int tx  = tid & 15;              // col group: cols tx*8..tx*8+7
    const int ty  = tid >> 4;              // row group: rows ty*8..ty*8+7
    const int row0 = blockIdx.x * GM;

    // Load indices for the two float4 fragments this thread stages per k-block.
    // idx = tid + it*256 in [0,512): r/o = idx>>2 (0..127), kq = idx&3.
    const int rA0 = (tid + 0)   >> 2, kq0 = (tid + 0)   & 3;
    const int rA1 = (tid + 256) >> 2, kq1 = (tid + 256) & 3;

    float acc[8][8];
    #pragma unroll
    for (int i = 0; i < 8; i++)
        #pragma unroll
        for (int j = 0; j < 8; j++) acc[i][j] = 0.0f;

    // Prologue: stage k-block 0 into registers
    float4 fa0, fa1, fw0, fw1;
    {
        fa0 = make_float4(0.f, 0.f, 0.f, 0.f);
        fa1 = fa0;
        if (row0 + rA0 < N) fa0 = *(const float4*)&feat[(size_t)(row0 + rA0) * IN_FEATS + (kq0 << 2)];
        if (row0 + rA1 < N) fa1 = *(const float4*)&feat[(size_t)(row0 + rA1) * IN_FEATS + (kq1 << 2)];
        fw0 = *(const float4*)&W[(size_t)rA0 * IN_FEATS + (kq0 << 2)];
        fw1 = *(const float4*)&W[(size_t)rA1 * IN_FEATS + (kq1 << 2)];
    }

    #pragma unroll 1
    for (int kb = 0; kb < IN_FEATS / GK; kb++) {
        // Commit staged registers to shared (transposed)
        As[(kq0 << 2) + 0][rA0] = fa0.x; As[(kq0 << 2) + 1][rA0] = fa0.y;
        As[(kq0 << 2) + 2][rA0] = fa0.z; As[(kq0 << 2) + 3][rA0] = fa0.w;
        As[(kq1 << 2) + 0][rA1] = fa1.x; As[(kq1 << 2) + 1][rA1] = fa1.y;
        As[(kq1 << 2) + 2][rA1] = fa1.z; As[(kq1 << 2) + 3][rA1] = fa1.w;
        Bs[(kq0 << 2) + 0][rA0] = fw0.x; Bs[(kq0 << 2) + 1][rA0] = fw0.y;
        Bs[(kq0 << 2) + 2][rA0] = fw0.z; Bs[(kq0 << 2) + 3][rA0] = fw0.w;
        Bs[(kq1 << 2) + 0][rA1] = fw1.x; Bs[(kq1 << 2) + 1][rA1] = fw1.y;
        Bs[(kq1 << 2) + 2][rA1] = fw1.z; Bs[(kq1 << 2) + 3][rA1] = fw1.w;
        __syncthreads();

        // Stage next k-block (LDG latency overlaps the FFMA block below)
        if (kb + 1 < IN_FEATS / GK) {
            int kc = (kb + 1) * GK;
            fa0 = make_float4(0.f, 0.f, 0.f, 0.f);
            fa1 = fa0;
            if (row0 + rA0 < N) fa0 = *(const float4*)&feat[(size_t)(row0 + rA0) * IN_FEATS + kc + (kq0 << 2)];
            if (row0 + rA1 < N) fa1 = *(const float4*)&feat[(size_t)(row0 + rA1) * IN_FEATS + kc + (kq1 << 2)];
            fw0 = *(const float4*)&W[(size_t)rA0 * IN_FEATS + kc + (kq0 << 2)];
            fw1 = *(const float4*)&W[(size_t)rA1 * IN_FEATS + kc + (kq1 << 2)];
        }

        #pragma unroll
        for (int k = 0; k < GK; k++) {
            float4 a0 = *(const float4*)&As[k][(ty << 3) + 0];
            float4 a1 = *(const float4*)&As[k][(ty << 3) + 4];
            float4 b0 = *(const float4*)&Bs[k][(tx << 3) + 0];
            float4 b1 = *(const float4*)&Bs[k][(tx << 3) + 4];
            float av[8] = {a0.x, a0.y, a0.z, a0.w, a1.x, a1.y, a1.z, a1.w};
            float bv[8] = {b0.x, b0.y, b0.z, b0.w, b1.x, b1.y, b1.z, b1.w};
            #pragma unroll
            for (int i = 0; i < 8; i++)
                #pragma unroll
                for (int j = 0; j < 8; j++)
                    acc[i][j] += av[i] * bv[j];
        }
        __syncthreads();
    }

    // Epilogue: write 8x8 microtile (two float4 per row)
    #pragma unroll
    for (int i = 0; i < 8; i++) {
        int r = row0 + (ty << 3) + i;
        if (r < N) {
            float4 v0 = make_float4(acc[i][0], acc[i][1], acc[i][2], acc[i][3]);
            float4 v1 = make_float4(acc[i][4], acc[i][5], acc[i][6], acc[i][7]);
            *(float4*)&g_ft[(size_t)r * HD + (tx << 3) + 0] = v0;
            *(float4*)&g_ft[(size_t)r * HD + (tx << 3) + 4] = v1;
        }
    }
}

// ---------------------------------------------------------------------------
// K5: atomic-free aggregation. One warp per DST node, software-pipelined.
// ft[dst] held in registers (1 float4/lane). No atomics anywhere.
// Max-subtraction skipped: mathematically identical softmax; |p*scale| <~ 7.
// ---------------------------------------------------------------------------
__global__ void agg_kernel(float* __restrict__ out, int N) {
    const int node = (blockIdx.x * blockDim.x + threadIdx.x) >> 5;
    if (node >= N) return;
    const int lane = threadIdx.x & 31;

    const int start = g_off[node];
    const int deg   = g_cnt[node];

    const float4* ft4 = (const float4*)g_ft;
    const float4 b4 = ft4[(size_t)node * 32 + lane];

    float4 acc = make_float4(0.f, 0.f, 0.f, 0.f);
    float s = 0.0f;
    const float scale = 0.17677669529663687f;  // 1/sqrt(32)

    for (int base = 0; base < deg; base += 32) {
        int j = base + lane;
        int sj = (j < deg) ? g_csr_src[start + j] : 0;
        int cnt = min(32, deg - base);

        int sn0 = __shfl_sync(0xffffffffu, sj, 0);
        float4 a4 = ft4[(size_t)sn0 * 32 + lane];

        #pragma unroll 2
        for (int t = 0; t < cnt; t++) {
            float4 cur = a4;
            if (t + 1 < cnt) {   // prefetch next edge's row
                int sn = __shfl_sync(0xffffffffu, sj, t + 1);
                a4 = ft4[(size_t)sn * 32 + lane];
            }
            float p = cur.x * b4.x + cur.y * b4.y + cur.z * b4.z + cur.w * b4.w;
            p += __shfl_xor_sync(0xffffffffu, p, 4);
            p += __shfl_xor_sync(0xffffffffu, p, 2);
            p += __shfl_xor_sync(0xffffffffu, p, 1);
            float e = __expf(p * scale);
            s += e;
            acc.x += e * cur.x; acc.y += e * cur.y;
            acc.z += e * cur.z; acc.w += e * cur.w;
        }
    }

    float inv = (deg > 0) ? (1.0f / s) : 0.0f;
    float4 r = make_float4(acc.x * inv, acc.y * inv, acc.z * inv, acc.w * inv);
    ((float4*)out)[(size_t)node * 32 + lane] = r;
}

// ---------------------------------------------------------------------------
extern "C" void kernel_launch(void* const* d_in, const int* in_sizes, int n_in,
                              void* d_out, int out_size) {
    const float* feat = (const float*)d_in[0];
    const float* W    = (const float*)d_in[1];
    const int*   src  = (const int*)d_in[2];
    const int*   dst  = (const int*)d_in[3];
    float* out = (float*)d_out;

    const int N = in_sizes[0] / IN_FEATS;   // 50000
    const int E = in_sizes[2];              // 800000

    const int nb = (N + SCAN_B - 1) / SCAN_B;

    // Persistent side stream + fork/join events (created once; resources only,
    // the captured work per call is identical every time).
    static cudaStream_t s_gemm = nullptr;
    static cudaEvent_t  ev_fork = nullptr, ev_join = nullptr;
    if (s_gemm == nullptr) {
        cudaStreamCreateWithFlags(&s_gemm, cudaStreamNonBlocking);
        cudaEventCreateWithFlags(&ev_fork, cudaEventDisableTiming);
        cudaEventCreateWithFlags(&ev_join, cudaEventDisableTiming);
    }

    // ---- fork: GEMM branch (depends only on feat, W) ----
    cudaEventRecord(ev_fork, 0);
    cudaStreamWaitEvent(s_gemm, ev_fork, 0);
    gemm_kernel<<<(N + GM - 1) / GM, 256, 0, s_gemm>>>(feat, W, N);
    cudaEventRecord(ev_join, s_gemm);

    // ---- main stream: CSR build branch (depends only on src, dst) ----
    zero_cnt_kernel<<<(N + 255) / 256, 256>>>(N);
    hist_kernel<<<(E + 255) / 256, 256>>>(dst, E);
    scan_phase1<<<nb, SCAN_B>>>(N);
    scan_phase2<<<1, 64>>>(nb);
    scan_phase3<<<nb, SCAN_B>>>(N);
    scatter_kernel<<<(E + 255) / 256, 256>>>(src, dst, E);

    // ---- join, then aggregate ----
    cudaStreamWaitEvent(0, ev_join, 0);
    {
        int warps_per_block = 8;  // 256 threads
        int blocks = (N + warps_per_block - 1) / warps_per_block;
        agg_kernel<<<blocks, 256>>>(out, N);
    }
}

// round 8
// speedup vs baseline: 1.7823x; 1.0081x over previous
#include <cuda_runtime.h>
#include <cuda_bf16.h>
#include <cstdint>

// Problem constants (fixed by the dataset)
#define N_NODES_MAX 50048
#define N_EDGES_MAX 800000
#define IN_FEATS    128
#define NUM_HEADS   4
#define OUT_FEATS   32
#define HD          (NUM_HEADS * OUT_FEATS)   // 128

#define SCAN_B 1024
#define MAX_BLOCKS ((N_NODES_MAX + SCAN_B - 1) / SCAN_B + 2)

// Scratch (static __device__ arrays; no allocation allowed)
__device__ float g_ft[N_NODES_MAX * HD];     // projected features [N,128]
__device__ int   g_cnt[N_NODES_MAX];         // in-degree histogram
__device__ int   g_off[N_NODES_MAX];         // CSR row starts
__device__ int   g_cur[N_NODES_MAX];         // scatter cursors
__device__ int   g_bsum[MAX_BLOCKS];         // per-block sums for scan
__device__ int   g_csr_src[N_EDGES_MAX];     // src node per CSR slot

// ---------------------------------------------------------------------------
// K1: in-degree histogram
// ---------------------------------------------------------------------------
__global__ void hist_kernel(const int* __restrict__ dst, int E) {
    int i = blockIdx.x * blockDim.x + threadIdx.x;
    if (i < E) atomicAdd(&g_cnt[dst[i]], 1);
}

// ---------------------------------------------------------------------------
// K2a: per-block sums for the scan
// ---------------------------------------------------------------------------
__global__ void scan_phase1(int N) {
    int i = blockIdx.x * SCAN_B + threadIdx.x;
    int v = (i < N) ? g_cnt[i] : 0;
    #pragma unroll
    for (int o = 16; o > 0; o >>= 1) v += __shfl_xor_sync(0xffffffffu, v, o);
    __shared__ int wsum[32];
    int lane = threadIdx.x & 31, w = threadIdx.x >> 5;
    if (lane == 0) wsum[w] = v;
    __syncthreads();
    if (w == 0) {
        int x = wsum[lane];
        #pragma unroll
        for (int o = 16; o > 0; o >>= 1) x += __shfl_xor_sync(0xffffffffu, x, o);
        if (lane == 0) g_bsum[blockIdx.x] = x;
    }
}

// ---------------------------------------------------------------------------
// K2b: per-block scan with inter-block base folded in (warp 0 sums g_bsum).
// ---------------------------------------------------------------------------
__global__ void scan_phase3(int N) {
    __shared__ int base_off;
    int lane = threadIdx.x & 31, w = threadIdx.x >> 5;
    if (threadIdx.x < 32) {
        int acc = 0;
        for (int j = lane; j < (int)blockIdx.x; j += 32) acc += g_bsum[j];
        #pragma unroll
        for (int o = 16; o > 0; o >>= 1) acc += __shfl_xor_sync(0xffffffffu, acc, o);
        if (lane == 0) base_off = acc;
    }
    int i = blockIdx.x * SCAN_B + threadIdx.x;
    int v = (i < N) ? g_cnt[i] : 0;
    int x = v;
    #pragma unroll
    for (int o = 1; o < 32; o <<= 1) {
        int y = __shfl_up_sync(0xffffffffu, x, o);
        if (lane >= o) x += y;
    }
    __shared__ int woff[32];
    if (lane == 31) woff[w] = x;
    __syncthreads();
    if (w == 0) {
        int y = woff[lane];
        int z = y;
        #pragma unroll
        for (int o = 1; o < 32; o <<= 1) {
            int t2 = __shfl_up_sync(0xffffffffu, z, o);
            if (lane >= o) z += t2;
        }
        woff[lane] = z - y;
    }
    __syncthreads();
    int excl = (x - v) + woff[w] + base_off;
    if (i < N) { g_off[i] = excl; g_cur[i] = excl; }
}

// ---------------------------------------------------------------------------
// K3: scatter src ids into CSR slots
// ---------------------------------------------------------------------------
__global__ void scatter_kernel(const int* __restrict__ src,
                               const int* __restrict__ dst, int E) {
    int i = blockIdx.x * blockDim.x + threadIdx.x;
    if (i < E) {
        int pos = atomicAdd(&g_cur[dst[i]], 1);
        g_csr_src[pos] = src[i];
    }
}

// ---------------------------------------------------------------------------
// K4: projection GEMM with packed fp32 (FFMA2). ft[n][o] = sum_k feat*W.
// 128x128 tile, BK=16, 256 threads, 8x8 microtile held as 8x4 f32x2 pairs:
// 32 fma.rn.f32x2 per k (vs 64 FFMA) -> 2x FMA-pipe throughput.
// B pairs are contiguous in Bs (pack = cheap mov.b64, ALU pipe);
// A broadcast-packed {a,a} once per k per row.
// Register-staged prefetch of k-block t+1 over compute of t.
// Runs on a forked stream, concurrent with the CSR build.
// ---------------------------------------------------------------------------
#define GM 128
#define GK 16
__global__ void __launch_bounds__(256, 2)
gemm_kernel(const float* __restrict__ feat,
            const float* __restrict__ W,
            int N) {
    __shared__ float As[GK][GM];    // feat tile, transposed: As[k][r]   8KB
    __shared__ float Bs[GK][HD];    // W tile, transposed:    Bs[k][o]   8KB

    const int tid = threadIdx.x;           // 0..255
    const int tx  = tid & 15;              // col group: cols tx*8..tx*8+7
    const int ty  = tid >> 4;              // row group: rows ty*8..ty*8+7
    const int row0 = blockIdx.x * GM;

    const int rA0 = (tid + 0)   >> 2, kq0 = (tid + 0)   & 3;
    const int rA1 = (tid + 256) >> 2, kq1 = (tid + 256) & 3;

    unsigned long long acc[8][4];   // 8 rows x 4 f32x2 pairs (= 8 cols)
    #pragma unroll
    for (int i = 0; i < 8; i++)
        #pragma unroll
        for (int j = 0; j < 4; j++) acc[i][j] = 0ULL;

    // Prologue: stage k-block 0 into registers
    float4 fa0, fa1, fw0, fw1;
    {
        fa0 = make_float4(0.f, 0.f, 0.f, 0.f);
        fa1 = fa0;
        if (row0 + rA0 < N) fa0 = *(const float4*)&feat[(size_t)(row0 + rA0) * IN_FEATS + (kq0 << 2)];
        if (row0 + rA1 < N) fa1 = *(const float4*)&feat[(size_t)(row0 + rA1) * IN_FEATS + (kq1 << 2)];
        fw0 = *(const float4*)&W[(size_t)rA0 * IN_FEATS + (kq0 << 2)];
        fw1 = *(const float4*)&W[(size_t)rA1 * IN_FEATS + (kq1 << 2)];
    }

    #pragma unroll 1
    for (int kb = 0; kb < IN_FEATS / GK; kb++) {
        // Commit staged registers to shared (transposed)
        As[(kq0 << 2) + 0][rA0] = fa0.x; As[(kq0 << 2) + 1][rA0] = fa0.y;
        As[(kq0 << 2) + 2][rA0] = fa0.z; As[(kq0 << 2) + 3][rA0] = fa0.w;
        As[(kq1 << 2) + 0][rA1] = fa1.x; As[(kq1 << 2) + 1][rA1] = fa1.y;
        As[(kq1 << 2) + 2][rA1] = fa1.z; As[(kq1 << 2) + 3][rA1] = fa1.w;
        Bs[(kq0 << 2) + 0][rA0] = fw0.x; Bs[(kq0 << 2) + 1][rA0] = fw0.y;
        Bs[(kq0 << 2) + 2][rA0] = fw0.z; Bs[(kq0 << 2) + 3][rA0] = fw0.w;
        Bs[(kq1 << 2) + 0][rA1] = fw1.x; Bs[(kq1 << 2) + 1][rA1] = fw1.y;
        Bs[(kq1 << 2) + 2][rA1] = fw1.z; Bs[(kq1 << 2) + 3][rA1] = fw1.w;
        __syncthreads();

        // Stage next k-block (LDG latency overlaps the FFMA2 block below)
        if (kb + 1 < IN_FEATS / GK) {
            int kc = (kb + 1) * GK;
            fa0 = make_float4(0.f, 0.f, 0.f, 0.f);
            fa1 = fa0;
            if (row0 + rA0 < N) fa0 = *(const float4*)&feat[(size_t)(row0 + rA0) * IN_FEATS + kc + (kq0 << 2)];
            if (row0 + rA1 < N) fa1 = *(const float4*)&feat[(size_t)(row0 + rA1) * IN_FEATS + kc + (kq1 << 2)];
            fw0 = *(const float4*)&W[(size_t)rA0 * IN_FEATS + kc + (kq0 << 2)];
            fw1 = *(const float4*)&W[(size_t)rA1 * IN_FEATS + kc + (kq1 << 2)];
        }

        #pragma unroll
        for (int k = 0; k < GK; k++) {
            float4 a0 = *(const float4*)&As[k][(ty << 3) + 0];
            float4 a1 = *(const float4*)&As[k][(ty << 3) + 4];
            float4 b0 = *(const float4*)&Bs[k][(tx << 3) + 0];
            float4 b1 = *(const float4*)&Bs[k][(tx << 3) + 4];
            unsigned long long bp[4];
            asm("mov.b64 %0, {%1, %2};" : "=l"(bp[0]) : "f"(b0.x), "f"(b0.y));
            asm("mov.b64 %0, {%1, %2};" : "=l"(bp[1]) : "f"(b0.z), "f"(b0.w));
            asm("mov.b64 %0, {%1, %2};" : "=l"(bp[2]) : "f"(b1.x), "f"(b1.y));
            asm("mov.b64 %0, {%1, %2};" : "=l"(bp[3]) : "f"(b1.z), "f"(b1.w));
            float av[8] = {a0.x, a0.y, a0.z, a0.w, a1.x, a1.y, a1.z, a1.w};
            #pragma unroll
            for (int i = 0; i < 8; i++) {
                unsigned long long ap;
                asm("mov.b64 %0, {%1, %1};" : "=l"(ap) : "f"(av[i]));
                #pragma unroll
                for (int jp = 0; jp < 4; jp++)
                    asm("fma.rn.f32x2 %0, %1, %2, %0;"
                        : "+l"(acc[i][jp]) : "l"(ap), "l"(bp[jp]));
            }
        }
        __syncthreads();
    }

    // Epilogue: each row's 4 u64 pairs == 8 contiguous floats; two STG.128.
    #pragma unroll
    for (int i = 0; i < 8; i++) {
        int r = row0 + (ty << 3) + i;
        if (r < N) {
            unsigned long long* d =
                (unsigned long long*)&g_ft[(size_t)r * HD + (tx << 3)];
            ulonglong2 v0; v0.x = acc[i][0]; v0.y = acc[i][1];
            ulonglong2 v1; v1.x = acc[i][2]; v1.y = acc[i][3];
            *(ulonglong2*)(d + 0) = v0;
            *(ulonglong2*)(d + 2) = v1;
        }
    }
}

// ---------------------------------------------------------------------------
// K5: atomic-free aggregation. One warp per DST node, software-pipelined.
// ft[dst] held in registers (1 float4/lane). No atomics anywhere.
// Max-subtraction skipped: mathematically identical softmax; |p*scale| <~ 7.
// ---------------------------------------------------------------------------
__global__ void agg_kernel(float* __restrict__ out, int N) {
    const int node = (blockIdx.x * blockDim.x + threadIdx.x) >> 5;
    if (node >= N) return;
    const int lane = threadIdx.x & 31;

    const int start = g_off[node];
    const int deg   = g_cnt[node];

    const float4* ft4 = (const float4*)g_ft;
    const float4 b4 = ft4[(size_t)node * 32 + lane];

    float4 acc = make_float4(0.f, 0.f, 0.f, 0.f);
    float s = 0.0f;
    const float scale = 0.17677669529663687f;  // 1/sqrt(32)

    for (int base = 0; base < deg; base += 32) {
        int j = base + lane;
        int sj = (j < deg) ? g_csr_src[start + j] : 0;
        int cnt = min(32, deg - base);

        int sn0 = __shfl_sync(0xffffffffu, sj, 0);
        float4 a4 = ft4[(size_t)sn0 * 32 + lane];

        #pragma unroll 2
        for (int t = 0; t < cnt; t++) {
            float4 cur = a4;
            if (t + 1 < cnt) {   // prefetch next edge's row
                int sn = __shfl_sync(0xffffffffu, sj, t + 1);
                a4 = ft4[(size_t)sn * 32 + lane];
            }
            float p = cur.x * b4.x + cur.y * b4.y + cur.z * b4.z + cur.w * b4.w;
            p += __shfl_xor_sync(0xffffffffu, p, 4);
            p += __shfl_xor_sync(0xffffffffu, p, 2);
            p += __shfl_xor_sync(0xffffffffu, p, 1);
            float e = __expf(p * scale);
            s += e;
            acc.x += e * cur.x; acc.y += e * cur.y;
            acc.z += e * cur.z; acc.w += e * cur.w;
        }
    }

    float inv = (deg > 0) ? (1.0f / s) : 0.0f;
    float4 r = make_float4(acc.x * inv, acc.y * inv, acc.z * inv, acc.w * inv);
    ((float4*)out)[(size_t)node * 32 + lane] = r;
}

// ---------------------------------------------------------------------------
extern "C" void kernel_launch(void* const* d_in, const int* in_sizes, int n_in,
                              void* d_out, int out_size) {
    const float* feat = (const float*)d_in[0];
    const float* W    = (const float*)d_in[1];
    const int*   src  = (const int*)d_in[2];
    const int*   dst  = (const int*)d_in[3];
    float* out = (float*)d_out;

    const int N = in_sizes[0] / IN_FEATS;   // 50000
    const int E = in_sizes[2];              // 800000
    const int nb = (N + SCAN_B - 1) / SCAN_B;

    // One-time resources (stream/events/symbol addr) — resources only;
    // the captured work per call is identical every time.
    static cudaStream_t s_gemm = nullptr;
    static cudaEvent_t  ev_fork = nullptr, ev_join = nullptr;
    static int* cnt_ptr = nullptr;
    if (s_gemm == nullptr) {
        cudaStreamCreateWithFlags(&s_gemm, cudaStreamNonBlocking);
        cudaEventCreateWithFlags(&ev_fork, cudaEventDisableTiming);
        cudaEventCreateWithFlags(&ev_join, cudaEventDisableTiming);
        cudaGetSymbolAddress((void**)&cnt_ptr, g_cnt);
    }

    // ---- fork: GEMM branch (depends only on feat, W) ----
    cudaEventRecord(ev_fork, 0);
    cudaStreamWaitEvent(s_gemm, ev_fork, 0);
    gemm_kernel<<<(N + GM - 1) / GM, 256, 0, s_gemm>>>(feat, W, N);
    cudaEventRecord(ev_join, s_gemm);

    // ---- main stream: CSR build branch (depends only on src, dst) ----
    cudaMemsetAsync(cnt_ptr, 0, (size_t)N * sizeof(int));
    hist_kernel<<<(E + 255) / 256, 256>>>(dst, E);
    scan_phase1<<<nb, SCAN_B>>>(N);
    scan_phase3<<<nb, SCAN_B>>>(N);
    scatter_kernel<<<(E + 255) / 256, 256>>>(src, dst, E);

    // ---- join, then aggregate ----
    cudaStreamWaitEvent(0, ev_join, 0);
    {
        int warps_per_block = 8;  // 256 threads
        int blocks = (N + warps_per_block - 1) / warps_per_block;
        agg_kernel<<<blocks, 256>>>(out, N);
    }
}